// round 1
// baseline (speedup 1.0000x reference)
#include <cuda_runtime.h>

#define NCLS 80
#define NCH  81
#define TK   100
#define BN   8
#define CN   256
#define HN   128
#define WN   128
#define HW   (HN*WN)

// ---------------- scratch (device globals: sanctioned, no allocs) ----------
__device__ float g_y[(size_t)BN*CN*HN*WN];      // relu(conv3x3) output, 512MB
__device__ float g_w1t[CN*9*CN];                // w1 transposed: [cin][tap][oc]
__device__ float g_w2t[CN*NCH];                 // w2 transposed: [cin][oc]
__device__ float g_pstar[BN*HW];
__device__ int   g_cls[BN*HW];
__device__ float g_scores[BN*HW];
__device__ int   g_topidx[BN*TK];

// ---------------- f32x2 helpers (Blackwell packed fp32) --------------------
__device__ __forceinline__ unsigned long long pk2(float lo, float hi){
    unsigned long long r;
    asm("mov.b64 %0, {%1,%2};" : "=l"(r) : "f"(lo), "f"(hi));
    return r;
}
__device__ __forceinline__ void upk2(unsigned long long v, float& lo, float& hi){
    asm("mov.b64 {%0,%1}, %2;" : "=f"(lo), "=f"(hi) : "l"(v));
}
__device__ __forceinline__ unsigned long long f2fma(unsigned long long a,
                                                    unsigned long long b,
                                                    unsigned long long c){
    unsigned long long d;
    asm("fma.rn.f32x2 %0, %1, %2, %3;" : "=l"(d) : "l"(a), "l"(b), "l"(c));
    return d;
}

// ---------------- K0: weight transposes ------------------------------------
__global__ void k0_transpose(const float* __restrict__ w1,
                             const float* __restrict__ w2){
    int t = blockIdx.x*256 + threadIdx.x;
    if (t < CN*9*CN){
        int cin = t/(9*CN); int tap = (t/CN)%9; int oc = t%CN;
        g_w1t[t] = w1[(oc*CN + cin)*9 + tap];
    }
    if (t < CN*NCH){
        int cin = t/NCH; int oc = t%NCH;
        g_w2t[t] = w2[oc*CN + cin];
    }
}

// ---------------- K1: conv3x3 + bias + relu (f32x2 packed) -----------------
// block: 64 oc x (8h x 16w) tile; 256 threads: tid = [ocg(4b)][row(3b)][pxg(1b)]
// each thread: 4 oc x 8 horizontally-adjacent pixels (4 f32x2 lanes)
__global__ __launch_bounds__(256,2) void k1_conv3(const float* __restrict__ x,
                                                  const float* __restrict__ b1){
    __shared__ __align__(16) float sIn[10][20];   // 10 rows x 18 used cols (padded)
    __shared__ __align__(16) float sW[9][64];     // [tap][oc_local]

    const int tid = threadIdx.x;
    const int bx  = blockIdx.x;
    const int h0  = (bx>>3)*8, w0 = (bx&7)*16;
    const int oc_base = blockIdx.y*64;
    const int b   = blockIdx.z;
    const int pxg = tid & 1, row = (tid>>1)&7, ocg = tid>>4;
    const int c0  = pxg*8;
    const float* xb = x + (size_t)b*CN*HW;

    unsigned long long acc[4][4];
    #pragma unroll
    for (int o=0;o<4;o++)
        #pragma unroll
        for (int q=0;q<4;q++) acc[o][q] = 0ull;

    // smem-fill coords (only tid<180 loads input)
    const int lr = tid/18, lc = tid%18;
    const int gh = h0 - 1 + lr, gw = w0 - 1 + lc;
    const bool inb = (tid<180) && (gh>=0) && (gh<HN) && (gw>=0) && (gw<WN);

    for (int cin=0; cin<CN; cin++){
        __syncthreads();
        if (tid < 180)
            sIn[lr][lc] = inb ? xb[(size_t)cin*HW + gh*WN + gw] : 0.f;
        #pragma unroll
        for (int i = tid; i < 576; i += 256)
            sW[i>>6][i&63] = g_w1t[(cin*9 + (i>>6))*CN + oc_base + (i&63)];
        __syncthreads();

        #pragma unroll
        for (int ky=0; ky<3; ky++){
            const float* rp = &sIn[row+ky][c0];
            float4 A  = *(const float4*)rp;
            float4 Bv = *(const float4*)(rp+4);
            float2 Cv = *(const float2*)(rp+8);
            const float i0=A.x,i1=A.y,i2=A.z,i3=A.w,i4=Bv.x,i5=Bv.y,i6=Bv.z,i7=Bv.w,i8=Cv.x,i9=Cv.y;
            unsigned long long P0[5], P1[4];
            P0[0]=pk2(i0,i1); P0[1]=pk2(i2,i3); P0[2]=pk2(i4,i5); P0[3]=pk2(i6,i7); P0[4]=pk2(i8,i9);
            P1[0]=pk2(i1,i2); P1[1]=pk2(i3,i4); P1[2]=pk2(i5,i6); P1[3]=pk2(i7,i8);
            #pragma unroll
            for (int o=0;o<4;o++){
                float wa = sW[ky*3+0][ocg*4+o];
                float wb = sW[ky*3+1][ocg*4+o];
                float wc = sW[ky*3+2][ocg*4+o];
                unsigned long long wpa = pk2(wa,wa), wpb = pk2(wb,wb), wpc = pk2(wc,wc);
                #pragma unroll
                for (int q=0;q<4;q++){
                    acc[o][q] = f2fma(wpa, P0[q],   acc[o][q]);
                    acc[o][q] = f2fma(wpb, P1[q],   acc[o][q]);
                    acc[o][q] = f2fma(wpc, P0[q+1], acc[o][q]);
                }
            }
        }
    }

    const int oh = h0 + row;
    #pragma unroll
    for (int o=0;o<4;o++){
        const int oc = oc_base + ocg*4 + o;
        const float bias = b1[oc];
        float* yp = g_y + (size_t)(b*CN + oc)*HW + oh*WN + w0 + c0;
        #pragma unroll
        for (int q=0;q<4;q++){
            float lo, hi; upk2(acc[o][q], lo, hi);
            lo = fmaxf(lo + bias, 0.f);
            hi = fmaxf(hi + bias, 0.f);
            *(float2*)(yp + 2*q) = make_float2(lo, hi);
        }
    }
}

// ---------------- K2: conv1x1 + bias + softmax stats + logits out ----------
__global__ __launch_bounds__(256) void k2_conv1(const float* __restrict__ b2,
                                                float* __restrict__ out){
    __shared__ __align__(16) float ws2[32][84];
    const int tid = threadIdx.x;
    const int gp  = blockIdx.x*256 + tid;
    const int b   = gp >> 14, hw = gp & (HW-1);

    float acc[NCH];
    #pragma unroll
    for (int o=0;o<NCH;o++) acc[o] = 0.f;

    const float* yb = g_y + (size_t)b*CN*HW + hw;
    for (int cc=0; cc<CN; cc+=32){
        __syncthreads();
        #pragma unroll
        for (int i=tid; i<32*NCH; i+=256)
            ws2[i/NCH][i%NCH] = g_w2t[(cc + i/NCH)*NCH + (i%NCH)];
        __syncthreads();
        #pragma unroll 4
        for (int cl=0; cl<32; cl++){
            const float yv = yb[(size_t)(cc+cl)*HW];
            #pragma unroll
            for (int o4=0;o4<20;o4++){
                float4 w4 = *(const float4*)&ws2[cl][o4*4];
                acc[o4*4+0] += yv*w4.x; acc[o4*4+1] += yv*w4.y;
                acc[o4*4+2] += yv*w4.z; acc[o4*4+3] += yv*w4.w;
            }
            acc[80] += yv*ws2[cl][80];
        }
    }
    #pragma unroll
    for (int o=0;o<NCH;o++) acc[o] += b2[o];

    float m = acc[0];
    #pragma unroll
    for (int o=1;o<NCH;o++) m = fmaxf(m, acc[o]);
    float s = 0.f;
    #pragma unroll
    for (int o=0;o<NCH;o++) s += expf(acc[o]-m);
    int cls = 0; float best = acc[0];
    #pragma unroll
    for (int o=1;o<NCLS;o++) if (acc[o] > best){ best = acc[o]; cls = o; }

    g_pstar[gp] = expf(best - m)/s;
    g_cls[gp]   = cls;

    float* lo = out + 409600 + (size_t)b*NCH*HW + hw;
    #pragma unroll
    for (int o=0;o<NCH;o++) lo[(size_t)o*HW] = acc[o];
}

// ---------------- K3: local-max boost + score map --------------------------
__global__ void k3_boost(){
    const int gp = blockIdx.x*256 + threadIdx.x;
    const int b = gp>>14, hw = gp&(HW-1);
    const int h = hw>>7,  w  = hw&127;
    const float p = g_pstar[gp];
    const int   c = g_cls[gp];
    bool ok = (p >= 1e-6f);
    #pragma unroll
    for (int dy=-1; dy<=1; dy++)
        #pragma unroll
        for (int dx=-1; dx<=1; dx++){
            if (dy==0 && dx==0) continue;
            int nh = h+dy, nw = w+dx;
            if (nh<0 || nh>=HN || nw<0 || nw>=WN) continue;
            int n = (b<<14) + nh*WN + nw;
            if (g_cls[n]==c && p < g_pstar[n]) ok = false;
        }
    g_scores[gp] = p + (ok ? 1.f : 0.f);
}

// ---------------- K4: per-batch top-100 via bitonic sort -------------------
// key = score_bits<<32 | (0xFFFFFFFF - idx) -> descending sort gives
// (score desc, idx asc) = jax.lax.top_k stable order
__global__ void k4_topk(){
    extern __shared__ unsigned long long sk[];
    const int N = HW;
    const int b = blockIdx.x, tid = threadIdx.x;
    for (int i=tid; i<N; i+=1024){
        unsigned sb = __float_as_uint(g_scores[(b<<14)+i]);  // scores > 0
        sk[i] = ((unsigned long long)sb<<32) | (unsigned)(0xFFFFFFFFu - (unsigned)i);
    }
    __syncthreads();
    for (int k=2; k<=N; k<<=1){
        for (int j=k>>1; j>0; j>>=1){
            for (int i=tid; i<N; i+=1024){
                int ixj = i^j;
                if (ixj > i){
                    unsigned long long a = sk[i], c = sk[ixj];
                    bool up = (i&k)==0;
                    if (up ? (a<c) : (a>c)){ sk[i]=c; sk[ixj]=a; }
                }
            }
            __syncthreads();
        }
    }
    if (tid < TK){
        unsigned low = (unsigned)sk[tid];
        g_topidx[b*TK + tid] = (int)(0xFFFFFFFFu - low);
    }
}

// ---------------- K5: gather proposals + pos embeddings --------------------
__global__ void k5_gather(const float* __restrict__ x,
                          const float* __restrict__ pe,
                          float* __restrict__ out){
    const int t = blockIdx.x*256 + threadIdx.x;
    if (t >= BN*CN*TK) return;
    const int k = t % TK;
    const int c = (t / TK) % CN;
    const int b = t / (TK*CN);
    const int idx = g_topidx[b*TK + k];
    out[t]            = x [(size_t)(b*CN + c)*HW + idx];
    out[BN*CN*TK + t] = pe[(size_t)c*HW + idx];
}

// ---------------- launch ----------------------------------------------------
extern "C" void kernel_launch(void* const* d_in, const int* in_sizes, int n_in,
                              void* d_out, int out_size){
    const float* x  = (const float*)d_in[0];
    const float* pe = (const float*)d_in[1];
    const float* w1 = (const float*)d_in[2];
    const float* b1 = (const float*)d_in[3];
    const float* w2 = (const float*)d_in[4];
    const float* b2 = (const float*)d_in[5];
    float* out = (float*)d_out;

    cudaFuncSetAttribute(k4_topk, cudaFuncAttributeMaxDynamicSharedMemorySize, 131072);

    k0_transpose<<<(CN*9*CN + 255)/256, 256>>>(w1, w2);

    dim3 g1(128, 4, 8);                 // 16x8 spatial tiles, 4 oc-tiles, 8 batches
    k1_conv3<<<g1, 256>>>(x, b1);

    k2_conv1<<<(BN*HW)/256, 256>>>(b2, out);
    k3_boost<<<(BN*HW)/256, 256>>>();
    k4_topk<<<BN, 1024, 131072>>>();
    k5_gather<<<(BN*CN*TK + 255)/256, 256>>>(x, pe, out);
}